// round 15
// baseline (speedup 1.0000x reference)
#include <cuda_runtime.h>
#include <cuda_bf16.h>
#include <math.h>
#include <cstdint>

#define N_UD   500000
#define N_USER 4000
#define N_SUP  300
#define H      128
#define HH     (H*H)
#define E_BIG  500000
#define E_SMALL 4000
#define SZ_U   (N_USER*H)
#define SZ_S   (N_SUP*H)
#define NA     (N_UD + N_USER)   // combined CSR key space
#define N_TILES 3907             // ceil(N_UD/128)

// ---------------- scratch (static __device__ -> no allocations) ----------------
// relu(hud1) stored pre-split as bf16 hi/lo (replaces fp32 hud1; same total bytes)
__device__ __align__(16) __nv_bfloat16 g_h1hi[(size_t)N_UD*H];
__device__ __align__(16) __nv_bfloat16 g_h1lo[(size_t)N_UD*H];
__device__ __align__(16) float g_user0[SZ_U];
__device__ __align__(16) float g_user1[SZ_U];
__device__ __align__(16) float g_sup0[SZ_S];
__device__ __align__(16) float g_sup1[SZ_S];
__device__ __align__(16) float g_tuser[SZ_U];

// fragment-ordered bf16-split weights for the two big GEMMs (mma B operand layout)
__device__ __align__(16) uint4 g_Bfh[2*2048];
__device__ __align__(16) uint4 g_Bfl[2*2048];

// combined CSR: keys [0,N_UD) = e1 by dst (vals = e1 src user)
//               keys [N_UD,NA) = e0 by dst user (vals = e0 src UD)
__device__ int g_cnt[NA];
__device__ int g_rowptr[NA];
__device__ int g_pos[NA];
__device__ int g_csrc[2*E_BIG];

// single-pass scan scratch
#define SCAN_T    1024
#define SCAN_IT   4
#define SCAN_BLK  124
__device__ int g_bsum[SCAN_BLK];
__device__ int g_arrive;

#define AGG_TOT (2*(2*SZ_U+SZ_S))
__device__ __align__(16) float g_agg[AGG_TOT];
#define L1_UB 0
#define L1_US (SZ_U)
#define L1_S  (2*SZ_U)
#define L2_UB (2*SZ_U+SZ_S)
#define L2_US (L2_UB+SZ_U)
#define L2_S  (L2_UB+2*SZ_U)

// ---------------- helpers ----------------
__device__ __forceinline__ uint32_t smem_to_u32(const void* p) {
    uint32_t a;
    asm("{ .reg .u64 t; cvta.to.shared.u64 t, %1; cvt.u32.u64 %0, t; }" : "=r"(a) : "l"(p));
    return a;
}
__device__ __forceinline__ void red_add_v4(float* p, float4 v) {
    asm volatile("red.global.add.v4.f32 [%0], {%1,%2,%3,%4};"
                 :: "l"(p), "f"(v.x), "f"(v.y), "f"(v.z), "f"(v.w) : "memory");
}
__device__ __forceinline__ void ldsm_x4(uint32_t* r, uint32_t addr) {
    asm volatile("ldmatrix.sync.aligned.m8n8.x4.shared.b16 {%0,%1,%2,%3}, [%4];"
        : "=r"(r[0]), "=r"(r[1]), "=r"(r[2]), "=r"(r[3]) : "r"(addr));
}
__device__ __forceinline__ void mma_bf16(float* d, const uint32_t* a, uint32_t b0, uint32_t b1) {
    asm volatile("mma.sync.aligned.m16n8k16.row.col.f32.bf16.bf16.f32 "
        "{%0,%1,%2,%3}, {%4,%5,%6,%7}, {%8,%9}, {%0,%1,%2,%3};"
        : "+f"(d[0]), "+f"(d[1]), "+f"(d[2]), "+f"(d[3])
        : "r"(a[0]), "r"(a[1]), "r"(a[2]), "r"(a[3]), "r"(b0), "r"(b1));
}

// ================= L1 combo: zero agg | prepW(frag) | gathers | hist =================
#define CB_Z   2075
#define CB_P   128
#define CB_G1  500
#define CB_G2  38
#define CB_H   1954
#define CB_TOT (CB_Z + CB_P + CB_G1 + CB_G2 + CB_H)

__global__ __launch_bounds__(256)
void k_combo(const float* __restrict__ Wt1, const float* __restrict__ Wt2,
             const float* __restrict__ emb_us, const int* __restrict__ nid_us,
             const float* __restrict__ emb_sp, const int* __restrict__ nid_sp,
             const int* __restrict__ e1d, const int* __restrict__ e0d) {
    int b = blockIdx.x, t = threadIdx.x;
    if (b < CB_Z) {
        int g = b*256 + t;
        if (g < AGG_TOT/4) ((float4*)g_agg)[g] = make_float4(0.f,0.f,0.f,0.f);
    } else if (b < CB_Z + CB_P) {
        int i = (b - CB_Z)*256 + t;
        int w = i >> 14;
        int r = i & (HH-1);
        int n = r >> 7, k = r & 127;
        const float* W = (w ? Wt2 : Wt1) + HH;
        float v = W[k*H + n];
        __nv_bfloat16 hi = __float2bfloat16(v);
        __nv_bfloat16 lo = __float2bfloat16(v - __bfloat162float(hi));
        int g16 = n >> 4, kc = k >> 4;
        int m = (((n >> 3) & 1) << 1) | ((k >> 3) & 1);
        int lane = ((n & 7) << 2) | ((k & 7) >> 1);
        int base = (((w*64 + g16*8 + kc)*32 + lane) << 2) | m;
        ((__nv_bfloat16*)g_Bfh)[base*2 + (k & 1)] = hi;
        ((__nv_bfloat16*)g_Bfl)[base*2 + (k & 1)] = lo;
    } else if (b < CB_Z + CB_P + CB_G1) {
        int g = (b - CB_Z - CB_P)*256 + t;
        int row = g >> 5, lane = g & 31;
        int r = nid_us[row];
        float4 v = *(const float4*)(emb_us + (size_t)r*H + lane*4);
        *(float4*)(g_user0 + (size_t)row*H + lane*4) = v;
    } else if (b < CB_Z + CB_P + CB_G1 + CB_G2) {
        int g = (b - CB_Z - CB_P - CB_G1)*256 + t;
        int row = g >> 5, lane = g & 31;
        if (row < N_SUP) {
            int r = nid_sp[row];
            float4 v = *(const float4*)(emb_sp + (size_t)r*H + lane*4);
            *(float4*)(g_sup0 + (size_t)row*H + lane*4) = v;
        }
    } else {
        int e = (b - CB_Z - CB_P - CB_G1 - CB_G2)*256 + t;
        if (e < E_BIG) {
            atomicAdd(&g_cnt[e1d[e]], 1);
            atomicAdd(&g_cnt[N_UD + e0d[e]], 1);
        }
    }
}

// ================= L2: single-kernel exclusive scan =================
__global__ __launch_bounds__(SCAN_T)
void k_scan1() {
    __shared__ int s[SCAN_T];
    __shared__ int sboff;
    int b = blockIdx.x, t = threadIdx.x;
    int base = b*(SCAN_T*SCAN_IT) + t*SCAN_IT;
    int v[SCAN_IT];
    #pragma unroll
    for (int i = 0; i < SCAN_IT; ++i) {
        int idx = base + i;
        v[i] = (idx < NA) ? g_cnt[idx] : 0;
    }
    int ts = v[0] + v[1] + v[2] + v[3];
    s[t] = ts; __syncthreads();
    #pragma unroll
    for (int o = 1; o < SCAN_T; o <<= 1) {
        int x = (t >= o) ? s[t-o] : 0;
        __syncthreads(); s[t] += x; __syncthreads();
    }
    int texcl = s[t] - ts;
    if (t == 0) {
        g_bsum[b] = s[SCAN_T-1];
        __threadfence();
        atomicAdd(&g_arrive, 1);
        while (atomicAdd(&g_arrive, 0) < gridDim.x) { }
        int sum = 0;
        for (int i = 0; i < b; ++i) sum += g_bsum[i];
        sboff = sum;
    }
    __syncthreads();
    int off = sboff + texcl;
    #pragma unroll
    for (int i = 0; i < SCAN_IT; ++i) {
        int idx = base + i;
        if (idx < NA) { g_rowptr[idx] = off; g_pos[idx] = off; }
        off += v[i];
    }
}

// ================= L3: CSR fill + tuser GEMM combined =================
#define FT_F   1954
#define FT_G   500
__global__ __launch_bounds__(256)
void k_fill_tuser(const int* __restrict__ e1s, const int* __restrict__ e1d,
                  const int* __restrict__ e0s, const int* __restrict__ e0d,
                  const float* __restrict__ A, const float* __restrict__ W) {
    int b = blockIdx.x, t = threadIdx.x;
    if (b < FT_F) {
        int e = b*256 + t;
        if (e < E_BIG) {
            int p = atomicAdd(&g_pos[e1d[e]], 1);
            g_csrc[p] = e1s[e];
            int q = atomicAdd(&g_pos[N_UD + e0d[e]], 1);
            g_csrc[q] = e0s[e];
        }
    } else {
        int g = (b - FT_F)*256 + t;
        int row = g >> 5, lane = g & 31;
        const float* a = A + (size_t)row*H;
        float4 acc = make_float4(0.f,0.f,0.f,0.f);
        #pragma unroll 8
        for (int k = 0; k < H; ++k) {
            float av = __ldg(a + k);
            float4 w = *(const float4*)(W + (size_t)k*H + lane*4);
            acc.x += av*w.x; acc.y += av*w.y; acc.z += av*w.z; acc.w += av*w.w;
        }
        *(float4*)(g_tuser + (size_t)row*H + lane*4) = acc;
    }
}

// ---------------- cleanup ----------------
__global__ void k_cleanup() {
    int g = blockIdx.x * blockDim.x + threadIdx.x;
    if (g < NA/4) ((int4*)g_cnt)[g] = make_int4(0,0,0,0);
    if (g == 0) g_arrive = 0;
}

// ---------------- edge scatter-add (small edge sets only) ----------------
__global__ void k_edge_add(const float* __restrict__ src_tab, const int* __restrict__ es,
                           const int* __restrict__ ed, float* __restrict__ dst_tab, int E) {
    int g = blockIdx.x * blockDim.x + threadIdx.x;
    int e = g >> 5;
    if (e >= E) return;
    int lane = g & 31;
    int s = es[e], d = ed[e];
    float4 v = *(const float4*)(src_tab + (size_t)s*H + lane*4);
    red_add_v4(dst_tab + (size_t)d*H + lane*4, v);
}

// ---------------- e0 L1 aggregation: recompute feat per edge ----------------
__global__ __launch_bounds__(128)
void k_agg_feat(const float* __restrict__ xud, const int* __restrict__ nid,
                const float* __restrict__ emb, const float* __restrict__ Wf,
                const float* __restrict__ bf,
                const int* __restrict__ rowptr, const int* __restrict__ csrc,
                float* __restrict__ aggUB) {
    __shared__ float sW[5*H];
    __shared__ float sb[H];
    int u = blockIdx.x;
    int t = threadIdx.x;
    for (int i = t; i < 5*H; i += 128) sW[i] = Wf[i];
    sb[t] = bf[t];
    __syncthreads();
    int beg = rowptr[N_UD + u];
    int end = (u == N_USER-1) ? 2*E_BIG : rowptr[N_UD + u + 1];
    float w0 = sW[0*H+t], w1 = sW[1*H+t], w2 = sW[2*H+t], w3 = sW[3*H+t], w4 = sW[4*H+t];
    float bb = sb[t];
    float acc = 0.f;
    #pragma unroll 2
    for (int e = beg; e < end; ++e) {
        int s = csrc[e];
        int nr = __ldg(nid + s);
        const float* xp = xud + (size_t)s*5;
        float x0 = __ldg(xp), x1 = __ldg(xp+1), x2 = __ldg(xp+2),
              x3 = __ldg(xp+3), x4 = __ldg(xp+4);
        float v = bb + emb[(size_t)nr*H + t]
                + x0*w0 + x1*w1 + x2*w2 + x3*w3 + x4*w4;
        acc += v;
    }
    aggUB[(size_t)u*H + t] = acc;
}

// ---------------- e0 L2 aggregation by gather (pre-split relu'd bf16) ----------------
__global__ __launch_bounds__(128)
void k_agg_user(const __nv_bfloat16* __restrict__ hi, const __nv_bfloat16* __restrict__ lo,
                const int* __restrict__ rowptr, const int* __restrict__ csrc,
                float* __restrict__ aggUB) {
    int u = blockIdx.x;
    int tid = threadIdx.x;
    int beg = rowptr[N_UD + u];
    int end = (u == N_USER-1) ? 2*E_BIG : rowptr[N_UD + u + 1];
    float acc = 0.f;
    int e = beg;
    for (; e + 4 <= end; e += 4) {
        size_t o0 = (size_t)csrc[e]*H + tid;
        size_t o1 = (size_t)csrc[e+1]*H + tid;
        size_t o2 = (size_t)csrc[e+2]*H + tid;
        size_t o3 = (size_t)csrc[e+3]*H + tid;
        float v0 = __bfloat162float(hi[o0]) + __bfloat162float(lo[o0]);
        float v1 = __bfloat162float(hi[o1]) + __bfloat162float(lo[o1]);
        float v2 = __bfloat162float(hi[o2]) + __bfloat162float(lo[o2]);
        float v3 = __bfloat162float(hi[o3]) + __bfloat162float(lo[o3]);
        acc += (v0 + v1) + (v2 + v3);
    }
    for (; e < end; ++e) {
        size_t o0 = (size_t)csrc[e]*H + tid;
        acc += __bfloat162float(hi[o0]) + __bfloat162float(lo[o0]);
    }
    aggUB[(size_t)u*H + tid] = acc;
}

// ---------------- small GEMM ----------------
__global__ void k_gemm_small(const float* __restrict__ A, const float* __restrict__ W,
                             const float* __restrict__ bias, float* __restrict__ C,
                             int M, int accum, int relu) {
    int g = blockIdx.x * blockDim.x + threadIdx.x;
    int row = g >> 5;
    if (row >= M) return;
    int lane = g & 31;
    const float* a = A + (size_t)row*H;
    float4 acc = make_float4(0.f,0.f,0.f,0.f);
    #pragma unroll 8
    for (int k = 0; k < H; ++k) {
        float av = __ldg(a + k);
        float4 w = *(const float4*)(W + (size_t)k*H + lane*4);
        acc.x += av*w.x; acc.y += av*w.y; acc.z += av*w.z; acc.w += av*w.w;
    }
    if (bias) {
        float4 b = *(const float4*)(bias + lane*4);
        acc.x += b.x; acc.y += b.y; acc.z += b.z; acc.w += b.w;
    }
    float* cp = C + (size_t)row*H + lane*4;
    if (accum) {
        float4 old = *(float4*)cp;
        acc.x += old.x; acc.y += old.y; acc.z += old.z; acc.w += old.w;
    }
    if (relu) { acc.x=fmaxf(acc.x,0.f); acc.y=fmaxf(acc.y,0.f); acc.z=fmaxf(acc.z,0.f); acc.w=fmaxf(acc.w,0.f); }
    *(float4*)cp = acc;
}

// ================= fused big GEMM: coalesced row-per-warp prologue/epilogue ==========
// MODE 1: A = feat(x_ud,Wf,bf,emb[nid]); out = relu(A@W + b + e1-CSR(tuser)) pre-split
//         to bf16 hi/lo arrays (h1hi/h1lo)
// MODE 2: A = pre-split relu'd hi/lo (straight copy to smem, no cvt);
//         C = A@W + b + e1-CSR(tuser); pred = log_softmax(C@Wout + bout)
#define PADB     272
#define SM_BIAS  0
#define SM_EX    512
#define SM_A     4096
#define SM_ALO   38912
#define SM_STAGE SM_A
#define TC_SMEM  73728
#define STG_STRIDE 132

template<int MODE>
__global__ __launch_bounds__(256, 2)
void k_fused_mma(const float* __restrict__ bias,
                 const float* __restrict__ tuser, const int* __restrict__ rowptr,
                 const int* __restrict__ csrc, float* __restrict__ C,
                 __nv_bfloat16* __restrict__ h1hi, __nv_bfloat16* __restrict__ h1lo,
                 const float* __restrict__ xud, const int* __restrict__ nid,
                 const float* __restrict__ emb, const float* __restrict__ Wf,
                 const float* __restrict__ bf,
                 const float* __restrict__ Wout, const float* __restrict__ bout,
                 float* __restrict__ pred, const uint4* __restrict__ Bfh,
                 const uint4* __restrict__ Bfl, int M) {
    extern __shared__ char smem[];
    uint32_t smem_base = smem_to_u32(smem);
    float* sBias = (float*)(smem + SM_BIAS);
    float* sEx   = (float*)(smem + SM_EX);

    int tid  = threadIdx.x;
    int wid  = tid >> 5;
    int lane = tid & 31;
    long blockRow = (long)blockIdx.x * 128;

    if (tid < 128) sBias[tid] = bias[tid];
    if (MODE == 1) {
        for (int i = tid; i < 768; i += 256) sEx[i] = (i < 640) ? Wf[i] : bf[i-640];
    } else {
        if (tid < 256) sEx[tid] = Wout[tid];
    }
    __syncthreads();

    // ---- prologue: row-per-warp, coalesced; each warp builds 16 rows ----
    {
        int kcol = lane*4;
        float4 we0, we1, we2, we3, we4, web;
        if (MODE == 1) {
            we0 = *(const float4*)(sEx + 0*H + kcol);
            we1 = *(const float4*)(sEx + 1*H + kcol);
            we2 = *(const float4*)(sEx + 2*H + kcol);
            we3 = *(const float4*)(sEx + 3*H + kcol);
            we4 = *(const float4*)(sEx + 4*H + kcol);
            web = *(const float4*)(sEx + 5*H + kcol);
        }
        #pragma unroll 4
        for (int i = 0; i < 16; ++i) {
            int prow = wid*16 + i;
            long rowReal = blockRow + prow;
            long rsrc = (rowReal < M) ? rowReal : (M-1);
            int off = prow*PADB + kcol*2;
            if (MODE == 1) {
                long nr = __ldg(nid + rsrc);
                const float* xp = xud + rsrc*5;
                float x0 = __ldg(xp), x1 = __ldg(xp+1), x2 = __ldg(xp+2),
                      x3 = __ldg(xp+3), x4 = __ldg(xp+4);
                float4 e = *(const float4*)(emb + nr*H + kcol);
                float4 o;
                o.x = web.x + e.x + x0*we0.x + x1*we1.x + x2*we2.x + x3*we3.x + x4*we4.x;
                o.y = web.y + e.y + x0*we0.y + x1*we1.y + x2*we2.y + x3*we3.y + x4*we4.y;
                o.z = web.z + e.z + x0*we0.z + x1*we1.z + x2*we2.z + x3*we3.z + x4*we4.z;
                o.w = web.w + e.w + x0*we0.w + x1*we1.w + x2*we2.w + x3*we3.w + x4*we4.w;
                uint32_t h0, h1;
                asm("cvt.rn.bf16x2.f32 %0, %1, %2;" : "=r"(h0) : "f"(o.y), "f"(o.x));
                asm("cvt.rn.bf16x2.f32 %0, %1, %2;" : "=r"(h1) : "f"(o.w), "f"(o.z));
                float hx = __uint_as_float(h0 << 16);
                float hy = __uint_as_float(h0 & 0xffff0000u);
                float hz = __uint_as_float(h1 << 16);
                float hw = __uint_as_float(h1 & 0xffff0000u);
                uint32_t l0, l1;
                asm("cvt.rn.bf16x2.f32 %0, %1, %2;" : "=r"(l0) : "f"(o.y - hy), "f"(o.x - hx));
                asm("cvt.rn.bf16x2.f32 %0, %1, %2;" : "=r"(l1) : "f"(o.w - hw), "f"(o.z - hz));
                uint2 hh; hh.x = h0; hh.y = h1;
                uint2 ll; ll.x = l0; ll.y = l1;
                *(uint2*)(smem + SM_A   + off) = hh;
                *(uint2*)(smem + SM_ALO + off) = ll;
            } else {
                uint2 hh = *(const uint2*)(h1hi + rsrc*H + kcol);
                uint2 ll = *(const uint2*)(h1lo + rsrc*H + kcol);
                *(uint2*)(smem + SM_A   + off) = hh;
                *(uint2*)(smem + SM_ALO + off) = ll;
            }
        }
    }
    __syncthreads();

    // ---- MMA mainloop: warp (wm, wn) owns 32 rows x 64 cols; B from global fragments ----
    int wm = wid & 3, wn = wid >> 2;
    float acc[2][8][4];
    #pragma unroll
    for (int mt = 0; mt < 2; ++mt)
        #pragma unroll
        for (int nt = 0; nt < 8; ++nt)
            #pragma unroll
            for (int q = 0; q < 4; ++q) acc[mt][nt][q] = 0.f;

    #pragma unroll
    for (int kc = 0; kc < 8; ++kc) {
        uint32_t ah[2][4], al[2][4];
        #pragma unroll
        for (int mt = 0; mt < 2; ++mt) {
            int row  = wm*32 + mt*16 + (lane & 15);
            int koff = kc*16 + (lane >> 4)*8;
            uint32_t off = row*PADB + koff*2;
            ldsm_x4(ah[mt], smem_base + SM_A   + off);
            ldsm_x4(al[mt], smem_base + SM_ALO + off);
        }
        #pragma unroll
        for (int g = 0; g < 4; ++g) {
            int gg = wn*4 + g;
            uint4 b4h = __ldg(&Bfh[(gg*8 + kc)*32 + lane]);
            uint4 b4l = __ldg(&Bfl[(gg*8 + kc)*32 + lane]);
            #pragma unroll
            for (int mt = 0; mt < 2; ++mt) {
                mma_bf16(acc[mt][2*g+0], ah[mt], b4h.x, b4h.y);
                mma_bf16(acc[mt][2*g+0], ah[mt], b4l.x, b4l.y);
                mma_bf16(acc[mt][2*g+0], al[mt], b4h.x, b4h.y);
                mma_bf16(acc[mt][2*g+1], ah[mt], b4h.z, b4h.w);
                mma_bf16(acc[mt][2*g+1], ah[mt], b4l.z, b4l.w);
                mma_bf16(acc[mt][2*g+1], al[mt], b4h.z, b4h.w);
            }
        }
    }

    // ---- stage accumulators to smem (overlays A) ----
    __syncthreads();
    float* stage = (float*)(smem + SM_STAGE);
    {
        int g = lane >> 2, t2 = (lane & 3)*2;
        #pragma unroll
        for (int mt = 0; mt < 2; ++mt) {
            #pragma unroll
            for (int nt = 0; nt < 8; ++nt) {
                int r0 = wm*32 + mt*16 + g;
                int c0 = wn*64 + nt*8 + t2;
                *(float2*)(stage + r0*STG_STRIDE + c0)     = make_float2(acc[mt][nt][0], acc[mt][nt][1]);
                *(float2*)(stage + (r0+8)*STG_STRIDE + c0) = make_float2(acc[mt][nt][2], acc[mt][nt][3]);
            }
        }
    }
    __syncthreads();

    // ---- epilogue: row-per-warp, coalesced ----
    {
        int kcol = lane*4;
        float4 b4 = *(const float4*)(sBias + kcol);
        float4 wa = make_float4(0,0,0,0), wb = make_float4(0,0,0,0);
        float bo0 = 0.f, bo1 = 0.f;
        if (MODE == 2) {
            wa = *(const float4*)(sEx + 2*kcol);
            wb = *(const float4*)(sEx + 2*kcol + 4);
            bo0 = bout[0]; bo1 = bout[1];
        }
        #pragma unroll 2
        for (int i = 0; i < 16; ++i) {
            int lrow = wid*16 + i;
            long orow = blockRow + lrow;
            bool ok = orow < M;
            long rc = ok ? orow : (M-1);
            int beg = __ldg(rowptr + rc);
            int end = __ldg(rowptr + rc + 1);
            float4 t4 = *(const float4*)(stage + lrow*STG_STRIDE + kcol);
            float4 v = make_float4(t4.x + b4.x, t4.y + b4.y, t4.z + b4.z, t4.w + b4.w);
            for (int e = beg; e < end; ++e) {
                float4 u = *(const float4*)(tuser + (size_t)csrc[e]*H + kcol);
                v.x += u.x; v.y += u.y; v.z += u.z; v.w += u.w;
            }
            if (MODE == 1) {
                if (ok) {
                    // relu + bf16 hi/lo split, store pre-split
                    float4 r = make_float4(fmaxf(v.x,0.f), fmaxf(v.y,0.f),
                                           fmaxf(v.z,0.f), fmaxf(v.w,0.f));
                    uint32_t h0, h1;
                    asm("cvt.rn.bf16x2.f32 %0, %1, %2;" : "=r"(h0) : "f"(r.y), "f"(r.x));
                    asm("cvt.rn.bf16x2.f32 %0, %1, %2;" : "=r"(h1) : "f"(r.w), "f"(r.z));
                    float hx = __uint_as_float(h0 << 16);
                    float hy = __uint_as_float(h0 & 0xffff0000u);
                    float hz = __uint_as_float(h1 << 16);
                    float hw = __uint_as_float(h1 & 0xffff0000u);
                    uint32_t l0, l1;
                    asm("cvt.rn.bf16x2.f32 %0, %1, %2;" : "=r"(l0) : "f"(r.y - hy), "f"(r.x - hx));
                    asm("cvt.rn.bf16x2.f32 %0, %1, %2;" : "=r"(l1) : "f"(r.w - hw), "f"(r.z - hz));
                    uint2 hh; hh.x = h0; hh.y = h1;
                    uint2 ll; ll.x = l0; ll.y = l1;
                    *(uint2*)(h1hi + orow*H + kcol) = hh;
                    *(uint2*)(h1lo + orow*H + kcol) = ll;
                }
            } else {
                if (ok) *(float4*)(C + orow*H + kcol) = v;
                float z0 = v.x*wa.x + v.y*wa.z + v.z*wb.x + v.w*wb.z;
                float z1 = v.x*wa.y + v.y*wa.w + v.z*wb.y + v.w*wb.w;
                #pragma unroll
                for (int o = 16; o > 0; o >>= 1) {
                    z0 += __shfl_xor_sync(0xffffffffu, z0, o);
                    z1 += __shfl_xor_sync(0xffffffffu, z1, o);
                }
                if (lane == 0 && ok) {
                    z0 += bo0; z1 += bo1;
                    float m = fmaxf(z0, z1);
                    float l = m + logf(expf(z0 - m) + expf(z1 - m));
                    *(float2*)(pred + orow*2) = make_float2(z0 - l, z1 - l);
                }
            }
        }
    }
}

// ---------------- launch ----------------
extern "C" void kernel_launch(void* const* d_in, const int* in_sizes, int n_in,
                              void* d_out, int out_size) {
    const float* x_ud   = (const float*)d_in[0];
    const float* W_feat = (const float*)d_in[1];
    const float* b_feat = (const float*)d_in[2];
    const float* emb_ud = (const float*)d_in[3];
    const float* emb_us = (const float*)d_in[4];
    const float* emb_sp = (const float*)d_in[5];
    const float* Wr1 = (const float*)d_in[6];
    const float* br1 = (const float*)d_in[7];
    const float* Wt1 = (const float*)d_in[8];
    const float* Wr2 = (const float*)d_in[9];
    const float* br2 = (const float*)d_in[10];
    const float* Wt2 = (const float*)d_in[11];
    const float* Wout = (const float*)d_in[12];
    const float* bout = (const float*)d_in[13];
    const int* nid_ud = (const int*)d_in[14];
    const int* nid_us = (const int*)d_in[15];
    const int* nid_sp = (const int*)d_in[16];
    const int* e0s = (const int*)d_in[17];
    const int* e0d = (const int*)d_in[18];
    const int* e1s = (const int*)d_in[19];
    const int* e1d = (const int*)d_in[20];
    const int* e2s = (const int*)d_in[21];
    const int* e2d = (const int*)d_in[22];
    const int* e3s = (const int*)d_in[23];
    const int* e3d = (const int*)d_in[24];

    float *p_user0, *p_user1, *p_sup0, *p_sup1, *p_tuser, *p_agg;
    int *p_rowptr, *p_csrc;
    uint4 *p_bfh, *p_bfl;
    __nv_bfloat16 *p_h1hi, *p_h1lo;
    cudaGetSymbolAddress((void**)&p_h1hi,  g_h1hi);
    cudaGetSymbolAddress((void**)&p_h1lo,  g_h1lo);
    cudaGetSymbolAddress((void**)&p_user0, g_user0);
    cudaGetSymbolAddress((void**)&p_user1, g_user1);
    cudaGetSymbolAddress((void**)&p_sup0,  g_sup0);
    cudaGetSymbolAddress((void**)&p_sup1,  g_sup1);
    cudaGetSymbolAddress((void**)&p_tuser, g_tuser);
    cudaGetSymbolAddress((void**)&p_agg,   g_agg);
    cudaGetSymbolAddress((void**)&p_rowptr, g_rowptr);
    cudaGetSymbolAddress((void**)&p_csrc,   g_csrc);
    cudaGetSymbolAddress((void**)&p_bfh,    g_Bfh);
    cudaGetSymbolAddress((void**)&p_bfl,    g_Bfl);

    float* out    = (float*)d_out;
    float* o_pred = out;
    float* o_hud  = out + 1000000;
    float* o_user = out + 65000000;
    float* o_sup  = out + 65512000;

    cudaFuncSetAttribute(k_fused_mma<1>, cudaFuncAttributeMaxDynamicSharedMemorySize, TC_SMEM);
    cudaFuncSetAttribute(k_fused_mma<2>, cudaFuncAttributeMaxDynamicSharedMemorySize, TC_SMEM);

    const int T = 256;
    int gridUs32  = (N_USER*32 + T-1)/T;
    int gridSp32  = (N_SUP*32 + T-1)/T;
    int gridES    = (E_SMALL*32 + T-1)/T;
    int gridClean = (NA/4 + T-1)/T;

    // ---- init (3 launches) ----
    k_combo<<<CB_TOT, T>>>(Wt1, Wt2, emb_us, nid_us, emb_sp, nid_sp, e1d, e0d);
    k_scan1<<<SCAN_BLK, SCAN_T>>>();
    k_fill_tuser<<<FT_F + FT_G, T>>>(e1s, e1d, e0s, e0d, p_user0, Wr1 + 1*HH);

    // ---- slot 4 (ncu-profiled next round): e0 L1 aggregation ----
    k_agg_feat<<<N_USER, 128>>>(x_ud, nid_ud, emb_ud, W_feat, b_feat,
                                p_rowptr, p_csrc, p_agg + L1_UB);

    // ---- layer 1 UD: fused feat+GEMM+e1 CSR -> pre-split relu bf16 ----
    k_fused_mma<1><<<N_TILES, 256, TC_SMEM>>>(
        br1 + 1*H, p_tuser, p_rowptr, p_csrc, nullptr,
        p_h1hi, p_h1lo, x_ud, nid_ud, emb_ud, W_feat, b_feat,
        nullptr, nullptr, nullptr, p_bfh, p_bfl, N_UD);

    // ---- layer 1 small aggregations ----
    k_edge_add<<<gridES, T>>>(p_sup0,  e3s, e3d, p_agg + L1_US, E_SMALL);
    k_edge_add<<<gridES, T>>>(p_user0, e2s, e2d, p_agg + L1_S,  E_SMALL);

    // ---- layer 1 user/sup outputs (post-relu stored) ----
    k_gemm_small<<<gridUs32, T>>>(p_agg + L1_UB, Wr1 + 0*HH, br1 + 0*H, p_user1, N_USER, 0, 0);
    k_gemm_small<<<gridUs32, T>>>(p_agg + L1_US, Wr1 + 3*HH, br1 + 3*H, p_user1, N_USER, 1, 0);
    k_gemm_small<<<gridUs32, T>>>(p_user0,       Wt1 + 0*HH, nullptr,   p_user1, N_USER, 1, 0);
    k_gemm_small<<<gridUs32, T>>>(p_user0,       Wt1 + 3*HH, nullptr,   p_user1, N_USER, 1, 1);
    k_gemm_small<<<gridSp32, T>>>(p_agg + L1_S,  Wr1 + 2*HH, br1 + 2*H, p_sup1,  N_SUP,  0, 0);
    k_gemm_small<<<gridSp32, T>>>(p_sup0,        Wt1 + 2*HH, nullptr,   p_sup1,  N_SUP,  1, 1);

    // ---- layer 2: tuser2, fused GEMM (pre-split A) + e1 CSR + pred ----
    k_gemm_small<<<gridUs32, T>>>(p_user1, Wr2 + 1*HH, nullptr, p_tuser, N_USER, 0, 0);
    k_fused_mma<2><<<N_TILES, 256, TC_SMEM>>>(
        br2 + 1*H, p_tuser, p_rowptr, p_csrc, o_hud,
        p_h1hi, p_h1lo, nullptr, nullptr, nullptr, nullptr, nullptr,
        Wout, bout, o_pred, p_bfh + 2048, p_bfl + 2048, N_UD);

    // ---- layer 2 aggregations + user/sup outputs ----
    k_agg_user<<<N_USER, 128>>>(p_h1hi, p_h1lo, p_rowptr, p_csrc, p_agg + L2_UB);
    k_edge_add<<<gridES, T>>>(p_sup1,  e3s, e3d, p_agg + L2_US, E_SMALL);
    k_edge_add<<<gridES, T>>>(p_user1, e2s, e2d, p_agg + L2_S,  E_SMALL);
    k_gemm_small<<<gridUs32, T>>>(p_agg + L2_UB, Wr2 + 0*HH, br2 + 0*H, o_user, N_USER, 0, 0);
    k_gemm_small<<<gridUs32, T>>>(p_agg + L2_US, Wr2 + 3*HH, br2 + 3*H, o_user, N_USER, 1, 0);
    k_gemm_small<<<gridUs32, T>>>(p_user1,       Wt2 + 0*HH, nullptr,   o_user, N_USER, 1, 0);
    k_gemm_small<<<gridUs32, T>>>(p_user1,       Wt2 + 3*HH, nullptr,   o_user, N_USER, 1, 0);
    k_gemm_small<<<gridSp32, T>>>(p_agg + L2_S,  Wr2 + 2*HH, br2 + 2*H, o_sup,  N_SUP,  0, 0);
    k_gemm_small<<<gridSp32, T>>>(p_sup1,        Wt2 + 2*HH, nullptr,   o_sup,  N_SUP,  1, 0);

    // ---- cleanup ----
    k_cleanup<<<gridClean, T>>>();

    (void)in_sizes; (void)n_in; (void)out_size;
}

// round 16
// speedup vs baseline: 1.1039x; 1.1039x over previous
#include <cuda_runtime.h>
#include <cuda_bf16.h>
#include <math.h>
#include <cstdint>

#define N_UD   500000
#define N_USER 4000
#define N_SUP  300
#define H      128
#define HH     (H*H)
#define E_BIG  500000
#define E_SMALL 4000
#define SZ_U   (N_USER*H)
#define SZ_S   (N_SUP*H)
#define NA     (N_UD + N_USER)   // combined CSR key space
#define N_TILES 3907             // ceil(N_UD/128)

// ---------------- scratch (static __device__ -> no allocations) ----------------
__device__ __align__(16) float g_hud1[(size_t)N_UD*H];
__device__ __align__(16) float g_user0[SZ_U];
__device__ __align__(16) float g_user1[SZ_U];
__device__ __align__(16) float g_sup0[SZ_S];
__device__ __align__(16) float g_sup1[SZ_S];
__device__ __align__(16) float g_tuser[SZ_U];

// fragment-ordered bf16-split weights for the two big GEMMs (mma B operand layout)
__device__ __align__(16) uint4 g_Bfh[2*2048];
__device__ __align__(16) uint4 g_Bfl[2*2048];

// combined CSR: keys [0,N_UD) = e1 by dst (vals = e1 src user)
//               keys [N_UD,NA) = e0 by dst user (vals = e0 src UD)
__device__ int g_cnt[NA];
__device__ int g_rowptr[NA];
__device__ int g_pos[NA];
__device__ int g_csrc[2*E_BIG];

// single-pass scan scratch
#define SCAN_T    1024
#define SCAN_IT   4
#define SCAN_BLK  124
__device__ int g_bsum[SCAN_BLK];
__device__ int g_arrive;

#define AGG_TOT (2*(2*SZ_U+SZ_S))
__device__ __align__(16) float g_agg[AGG_TOT];
#define L1_UB 0
#define L1_US (SZ_U)
#define L1_S  (2*SZ_U)
#define L2_UB (2*SZ_U+SZ_S)
#define L2_US (L2_UB+SZ_U)
#define L2_S  (L2_UB+2*SZ_U)

// ---------------- helpers ----------------
__device__ __forceinline__ uint32_t smem_to_u32(const void* p) {
    uint32_t a;
    asm("{ .reg .u64 t; cvta.to.shared.u64 t, %1; cvt.u32.u64 %0, t; }" : "=r"(a) : "l"(p));
    return a;
}
__device__ __forceinline__ void red_add_v4(float* p, float4 v) {
    asm volatile("red.global.add.v4.f32 [%0], {%1,%2,%3,%4};"
                 :: "l"(p), "f"(v.x), "f"(v.y), "f"(v.z), "f"(v.w) : "memory");
}
__device__ __forceinline__ void ldsm_x4(uint32_t* r, uint32_t addr) {
    asm volatile("ldmatrix.sync.aligned.m8n8.x4.shared.b16 {%0,%1,%2,%3}, [%4];"
        : "=r"(r[0]), "=r"(r[1]), "=r"(r[2]), "=r"(r[3]) : "r"(addr));
}
__device__ __forceinline__ void mma_bf16(float* d, const uint32_t* a, uint32_t b0, uint32_t b1) {
    asm volatile("mma.sync.aligned.m16n8k16.row.col.f32.bf16.bf16.f32 "
        "{%0,%1,%2,%3}, {%4,%5,%6,%7}, {%8,%9}, {%0,%1,%2,%3};"
        : "+f"(d[0]), "+f"(d[1]), "+f"(d[2]), "+f"(d[3])
        : "r"(a[0]), "r"(a[1]), "r"(a[2]), "r"(a[3]), "r"(b0), "r"(b1));
}

// ================= L1 combo: zero agg | prepW(frag) | gathers | hist =================
#define CB_Z   2075
#define CB_P   128
#define CB_G1  500
#define CB_G2  38
#define CB_H   1954
#define CB_TOT (CB_Z + CB_P + CB_G1 + CB_G2 + CB_H)

__global__ __launch_bounds__(256)
void k_combo(const float* __restrict__ Wt1, const float* __restrict__ Wt2,
             const float* __restrict__ emb_us, const int* __restrict__ nid_us,
             const float* __restrict__ emb_sp, const int* __restrict__ nid_sp,
             const int* __restrict__ e1d, const int* __restrict__ e0d) {
    int b = blockIdx.x, t = threadIdx.x;
    if (b < CB_Z) {
        int g = b*256 + t;
        if (g < AGG_TOT/4) ((float4*)g_agg)[g] = make_float4(0.f,0.f,0.f,0.f);
    } else if (b < CB_Z + CB_P) {
        int i = (b - CB_Z)*256 + t;
        int w = i >> 14;
        int r = i & (HH-1);
        int n = r >> 7, k = r & 127;
        const float* W = (w ? Wt2 : Wt1) + HH;
        float v = W[k*H + n];
        __nv_bfloat16 hi = __float2bfloat16(v);
        __nv_bfloat16 lo = __float2bfloat16(v - __bfloat162float(hi));
        int g16 = n >> 4, kc = k >> 4;
        int m = (((n >> 3) & 1) << 1) | ((k >> 3) & 1);
        int lane = ((n & 7) << 2) | ((k & 7) >> 1);
        int base = (((w*64 + g16*8 + kc)*32 + lane) << 2) | m;
        ((__nv_bfloat16*)g_Bfh)[base*2 + (k & 1)] = hi;
        ((__nv_bfloat16*)g_Bfl)[base*2 + (k & 1)] = lo;
    } else if (b < CB_Z + CB_P + CB_G1) {
        int g = (b - CB_Z - CB_P)*256 + t;
        int row = g >> 5, lane = g & 31;
        int r = nid_us[row];
        float4 v = *(const float4*)(emb_us + (size_t)r*H + lane*4);
        *(float4*)(g_user0 + (size_t)row*H + lane*4) = v;
    } else if (b < CB_Z + CB_P + CB_G1 + CB_G2) {
        int g = (b - CB_Z - CB_P - CB_G1)*256 + t;
        int row = g >> 5, lane = g & 31;
        if (row < N_SUP) {
            int r = nid_sp[row];
            float4 v = *(const float4*)(emb_sp + (size_t)r*H + lane*4);
            *(float4*)(g_sup0 + (size_t)row*H + lane*4) = v;
        }
    } else {
        int e = (b - CB_Z - CB_P - CB_G1 - CB_G2)*256 + t;
        if (e < E_BIG) {
            atomicAdd(&g_cnt[e1d[e]], 1);
            atomicAdd(&g_cnt[N_UD + e0d[e]], 1);
        }
    }
}

// ================= L2: single-kernel exclusive scan =================
__global__ __launch_bounds__(SCAN_T)
void k_scan1() {
    __shared__ int s[SCAN_T];
    __shared__ int sboff;
    int b = blockIdx.x, t = threadIdx.x;
    int base = b*(SCAN_T*SCAN_IT) + t*SCAN_IT;
    int v[SCAN_IT];
    #pragma unroll
    for (int i = 0; i < SCAN_IT; ++i) {
        int idx = base + i;
        v[i] = (idx < NA) ? g_cnt[idx] : 0;
    }
    int ts = v[0] + v[1] + v[2] + v[3];
    s[t] = ts; __syncthreads();
    #pragma unroll
    for (int o = 1; o < SCAN_T; o <<= 1) {
        int x = (t >= o) ? s[t-o] : 0;
        __syncthreads(); s[t] += x; __syncthreads();
    }
    int texcl = s[t] - ts;
    if (t == 0) {
        g_bsum[b] = s[SCAN_T-1];
        __threadfence();
        atomicAdd(&g_arrive, 1);
        while (atomicAdd(&g_arrive, 0) < gridDim.x) { }
        int sum = 0;
        for (int i = 0; i < b; ++i) sum += g_bsum[i];
        sboff = sum;
    }
    __syncthreads();
    int off = sboff + texcl;
    #pragma unroll
    for (int i = 0; i < SCAN_IT; ++i) {
        int idx = base + i;
        if (idx < NA) { g_rowptr[idx] = off; g_pos[idx] = off; }
        off += v[i];
    }
}

// ================= L3: CSR fill + tuser GEMM combined =================
#define FT_F   1954
#define FT_G   500
__global__ __launch_bounds__(256)
void k_fill_tuser(const int* __restrict__ e1s, const int* __restrict__ e1d,
                  const int* __restrict__ e0s, const int* __restrict__ e0d,
                  const float* __restrict__ A, const float* __restrict__ W) {
    int b = blockIdx.x, t = threadIdx.x;
    if (b < FT_F) {
        int e = b*256 + t;
        if (e < E_BIG) {
            int p = atomicAdd(&g_pos[e1d[e]], 1);
            g_csrc[p] = e1s[e];
            int q = atomicAdd(&g_pos[N_UD + e0d[e]], 1);
            g_csrc[q] = e0s[e];
        }
    } else {
        int g = (b - FT_F)*256 + t;
        int row = g >> 5, lane = g & 31;
        const float* a = A + (size_t)row*H;
        float4 acc = make_float4(0.f,0.f,0.f,0.f);
        #pragma unroll 8
        for (int k = 0; k < H; ++k) {
            float av = __ldg(a + k);
            float4 w = *(const float4*)(W + (size_t)k*H + lane*4);
            acc.x += av*w.x; acc.y += av*w.y; acc.z += av*w.z; acc.w += av*w.w;
        }
        *(float4*)(g_tuser + (size_t)row*H + lane*4) = acc;
    }
}

// ---------------- cleanup ----------------
__global__ void k_cleanup() {
    int g = blockIdx.x * blockDim.x + threadIdx.x;
    if (g < NA/4) ((int4*)g_cnt)[g] = make_int4(0,0,0,0);
    if (g == 0) g_arrive = 0;
}

// ---------------- edge scatter-add (small edge sets only) ----------------
__global__ void k_edge_add(const float* __restrict__ src_tab, const int* __restrict__ es,
                           const int* __restrict__ ed, float* __restrict__ dst_tab, int E) {
    int g = blockIdx.x * blockDim.x + threadIdx.x;
    int e = g >> 5;
    if (e >= E) return;
    int lane = g & 31;
    int s = es[e], d = ed[e];
    float4 v = *(const float4*)(src_tab + (size_t)s*H + lane*4);
    red_add_v4(dst_tab + (size_t)d*H + lane*4, v);
}

// ---------------- e0 L1 aggregation: algebraic split + 8-deep gather ----------------
// agg[u] = (Σ_e x[s_e]) @ Wf + cnt*bf + Σ_e emb[nid[s_e]]
__global__ __launch_bounds__(128)
void k_agg_feat(const float* __restrict__ xud, const int* __restrict__ nid,
                const float* __restrict__ emb, const float* __restrict__ Wf,
                const float* __restrict__ bf,
                const int* __restrict__ rowptr, const int* __restrict__ csrc,
                float* __restrict__ aggUB) {
    __shared__ float sred[4][5];
    int u = blockIdx.x;
    int t = threadIdx.x;
    int lane = t & 31, w = t >> 5;
    int beg = rowptr[N_UD + u];
    int end = (u == N_USER-1) ? 2*E_BIG : rowptr[N_UD + u + 1];

    // phase 1: x-sum over edges (5 floats)
    float lx[5] = {0.f, 0.f, 0.f, 0.f, 0.f};
    for (int e = beg + t; e < end; e += 128) {
        const float* xp = xud + (size_t)csrc[e]*5;
        lx[0] += __ldg(xp);   lx[1] += __ldg(xp+1); lx[2] += __ldg(xp+2);
        lx[3] += __ldg(xp+3); lx[4] += __ldg(xp+4);
    }
    #pragma unroll
    for (int j = 0; j < 5; ++j)
        #pragma unroll
        for (int o = 16; o > 0; o >>= 1)
            lx[j] += __shfl_xor_sync(0xffffffffu, lx[j], o);
    if (lane == 0) {
        sred[w][0]=lx[0]; sred[w][1]=lx[1]; sred[w][2]=lx[2];
        sred[w][3]=lx[3]; sred[w][4]=lx[4];
    }
    __syncthreads();

    // phase 2: emb row gather, 8-deep MLP
    float acc = 0.f;
    int e = beg;
    for (; e + 8 <= end; e += 8) {
        int n0 = __ldg(nid + csrc[e+0]);
        int n1 = __ldg(nid + csrc[e+1]);
        int n2 = __ldg(nid + csrc[e+2]);
        int n3 = __ldg(nid + csrc[e+3]);
        int n4 = __ldg(nid + csrc[e+4]);
        int n5 = __ldg(nid + csrc[e+5]);
        int n6 = __ldg(nid + csrc[e+6]);
        int n7 = __ldg(nid + csrc[e+7]);
        float v0 = emb[(size_t)n0*H + t];
        float v1 = emb[(size_t)n1*H + t];
        float v2 = emb[(size_t)n2*H + t];
        float v3 = emb[(size_t)n3*H + t];
        float v4 = emb[(size_t)n4*H + t];
        float v5 = emb[(size_t)n5*H + t];
        float v6 = emb[(size_t)n6*H + t];
        float v7 = emb[(size_t)n7*H + t];
        acc += ((v0+v1) + (v2+v3)) + ((v4+v5) + (v6+v7));
    }
    for (; e < end; ++e)
        acc += emb[(size_t)__ldg(nid + csrc[e])*H + t];

    float sx0 = sred[0][0]+sred[1][0]+sred[2][0]+sred[3][0];
    float sx1 = sred[0][1]+sred[1][1]+sred[2][1]+sred[3][1];
    float sx2 = sred[0][2]+sred[1][2]+sred[2][2]+sred[3][2];
    float sx3 = sred[0][3]+sred[1][3]+sred[2][3]+sred[3][3];
    float sx4 = sred[0][4]+sred[1][4]+sred[2][4]+sred[3][4];
    float cnt = (float)(end - beg);
    acc += cnt*__ldg(bf + t)
         + sx0*__ldg(Wf + 0*H + t) + sx1*__ldg(Wf + 1*H + t)
         + sx2*__ldg(Wf + 2*H + t) + sx3*__ldg(Wf + 3*H + t)
         + sx4*__ldg(Wf + 4*H + t);
    aggUB[(size_t)u*H + t] = acc;
}

// ---------------- e0 L2 aggregation by gather (relu(hud1)) ----------------
__global__ __launch_bounds__(128)
void k_agg_user(const float* __restrict__ hud, const int* __restrict__ rowptr,
                const int* __restrict__ csrc, float* __restrict__ aggUB) {
    int u = blockIdx.x;
    int tid = threadIdx.x;
    int beg = rowptr[N_UD + u];
    int end = (u == N_USER-1) ? 2*E_BIG : rowptr[N_UD + u + 1];
    float acc = 0.f;
    int e = beg;
    for (; e + 8 <= end; e += 8) {
        int s0 = csrc[e+0], s1 = csrc[e+1], s2 = csrc[e+2], s3 = csrc[e+3];
        int s4 = csrc[e+4], s5 = csrc[e+5], s6 = csrc[e+6], s7 = csrc[e+7];
        float v0 = fmaxf(hud[(size_t)s0*H + tid], 0.f);
        float v1 = fmaxf(hud[(size_t)s1*H + tid], 0.f);
        float v2 = fmaxf(hud[(size_t)s2*H + tid], 0.f);
        float v3 = fmaxf(hud[(size_t)s3*H + tid], 0.f);
        float v4 = fmaxf(hud[(size_t)s4*H + tid], 0.f);
        float v5 = fmaxf(hud[(size_t)s5*H + tid], 0.f);
        float v6 = fmaxf(hud[(size_t)s6*H + tid], 0.f);
        float v7 = fmaxf(hud[(size_t)s7*H + tid], 0.f);
        acc += ((v0+v1) + (v2+v3)) + ((v4+v5) + (v6+v7));
    }
    for (; e < end; ++e) acc += fmaxf(hud[(size_t)csrc[e]*H + tid], 0.f);
    aggUB[(size_t)u*H + tid] = acc;
}

// ---------------- small GEMM ----------------
__global__ void k_gemm_small(const float* __restrict__ A, const float* __restrict__ W,
                             const float* __restrict__ bias, float* __restrict__ C,
                             int M, int accum, int relu) {
    int g = blockIdx.x * blockDim.x + threadIdx.x;
    int row = g >> 5;
    if (row >= M) return;
    int lane = g & 31;
    const float* a = A + (size_t)row*H;
    float4 acc = make_float4(0.f,0.f,0.f,0.f);
    #pragma unroll 8
    for (int k = 0; k < H; ++k) {
        float av = __ldg(a + k);
        float4 w = *(const float4*)(W + (size_t)k*H + lane*4);
        acc.x += av*w.x; acc.y += av*w.y; acc.z += av*w.z; acc.w += av*w.w;
    }
    if (bias) {
        float4 b = *(const float4*)(bias + lane*4);
        acc.x += b.x; acc.y += b.y; acc.z += b.z; acc.w += b.w;
    }
    float* cp = C + (size_t)row*H + lane*4;
    if (accum) {
        float4 old = *(float4*)cp;
        acc.x += old.x; acc.y += old.y; acc.z += old.z; acc.w += old.w;
    }
    if (relu) { acc.x=fmaxf(acc.x,0.f); acc.y=fmaxf(acc.y,0.f); acc.z=fmaxf(acc.z,0.f); acc.w=fmaxf(acc.w,0.f); }
    *(float4*)cp = acc;
}

// ================= fused big GEMM: coalesced row-per-warp prologue/epilogue ==========
// smem = 73.7KB -> 2 CTAs/SM; B fragments from global (L1-hot)
// MODE 1: A = feat(x_ud,Wf,bf,emb[nid]); C = A@W + b + e1-CSR(tuser)
// MODE 2: A = relu(Ain); C = A@W + b + e1-CSR(tuser); pred = log_softmax(C@Wout + bout)
#define PADB     272
#define SM_BIAS  0
#define SM_EX    512
#define SM_A     4096
#define SM_ALO   38912
#define SM_STAGE SM_A
#define TC_SMEM  73728
#define STG_STRIDE 132

template<int MODE>
__global__ __launch_bounds__(256, 2)
void k_fused_mma(const float* __restrict__ bias,
                 const float* __restrict__ tuser, const int* __restrict__ rowptr,
                 const int* __restrict__ csrc, float* __restrict__ C,
                 const float* __restrict__ Ain,
                 const float* __restrict__ xud, const int* __restrict__ nid,
                 const float* __restrict__ emb, const float* __restrict__ Wf,
                 const float* __restrict__ bf,
                 const float* __restrict__ Wout, const float* __restrict__ bout,
                 float* __restrict__ pred, const uint4* __restrict__ Bfh,
                 const uint4* __restrict__ Bfl, int M) {
    extern __shared__ char smem[];
    uint32_t smem_base = smem_to_u32(smem);
    float* sBias = (float*)(smem + SM_BIAS);
    float* sEx   = (float*)(smem + SM_EX);

    int tid  = threadIdx.x;
    int wid  = tid >> 5;
    int lane = tid & 31;
    long blockRow = (long)blockIdx.x * 128;

    if (tid < 128) sBias[tid] = bias[tid];
    if (MODE == 1) {
        for (int i = tid; i < 768; i += 256) sEx[i] = (i < 640) ? Wf[i] : bf[i-640];
    } else {
        if (tid < 256) sEx[tid] = Wout[tid];
    }
    __syncthreads();

    // ---- prologue: row-per-warp, coalesced; each warp builds 16 rows ----
    {
        int kcol = lane*4;
        float4 we0, we1, we2, we3, we4, web;
        if (MODE == 1) {
            we0 = *(const float4*)(sEx + 0*H + kcol);
            we1 = *(const float4*)(sEx + 1*H + kcol);
            we2 = *(const float4*)(sEx + 2*H + kcol);
            we3 = *(const float4*)(sEx + 3*H + kcol);
            we4 = *(const float4*)(sEx + 4*H + kcol);
            web = *(const float4*)(sEx + 5*H + kcol);
        }
        #pragma unroll 4
        for (int i = 0; i < 16; ++i) {
            int prow = wid*16 + i;
            long rowReal = blockRow + prow;
            long rsrc = (rowReal < M) ? rowReal : (M-1);
            float4 o;
            if (MODE == 1) {
                long nr = __ldg(nid + rsrc);
                const float* xp = xud + rsrc*5;
                float x0 = __ldg(xp), x1 = __ldg(xp+1), x2 = __ldg(xp+2),
                      x3 = __ldg(xp+3), x4 = __ldg(xp+4);
                float4 e = *(const float4*)(emb + nr*H + kcol);
                o.x = web.x + e.x + x0*we0.x + x1*we1.x + x2*we2.x + x3*we3.x + x4*we4.x;
                o.y = web.y + e.y + x0*we0.y + x1*we1.y + x2*we2.y + x3*we3.y + x4*we4.y;
                o.z = web.z + e.z + x0*we0.z + x1*we1.z + x2*we2.z + x3*we3.z + x4*we4.z;
                o.w = web.w + e.w + x0*we0.w + x1*we1.w + x2*we2.w + x3*we3.w + x4*we4.w;
            } else {
                o = *(const float4*)(Ain + rsrc*H + kcol);
                o.x=fmaxf(o.x,0.f); o.y=fmaxf(o.y,0.f); o.z=fmaxf(o.z,0.f); o.w=fmaxf(o.w,0.f);
            }
            uint32_t h0, h1;
            asm("cvt.rn.bf16x2.f32 %0, %1, %2;" : "=r"(h0) : "f"(o.y), "f"(o.x));
            asm("cvt.rn.bf16x2.f32 %0, %1, %2;" : "=r"(h1) : "f"(o.w), "f"(o.z));
            float hx = __uint_as_float(h0 << 16);
            float hy = __uint_as_float(h0 & 0xffff0000u);
            float hz = __uint_as_float(h1 << 16);
            float hw = __uint_as_float(h1 & 0xffff0000u);
            uint32_t l0, l1;
            asm("cvt.rn.bf16x2.f32 %0, %1, %2;" : "=r"(l0) : "f"(o.y - hy), "f"(o.x - hx));
            asm("cvt.rn.bf16x2.f32 %0, %1, %2;" : "=r"(l1) : "f"(o.w - hw), "f"(o.z - hz));
            uint2 hh; hh.x = h0; hh.y = h1;
            uint2 ll; ll.x = l0; ll.y = l1;
            int off = prow*PADB + kcol*2;
            *(uint2*)(smem + SM_A   + off) = hh;
            *(uint2*)(smem + SM_ALO + off) = ll;
        }
    }
    __syncthreads();

    // ---- MMA mainloop: warp (wm, wn) owns 32 rows x 64 cols; B from global fragments ----
    int wm = wid & 3, wn = wid >> 2;
    float acc[2][8][4];
    #pragma unroll
    for (int mt = 0; mt < 2; ++mt)
        #pragma unroll
        for (int nt = 0; nt < 8; ++nt)
            #pragma unroll
            for (int q = 0; q < 4; ++q) acc[mt][nt][q] = 0.f;

    #pragma unroll
    for (int kc = 0; kc < 8; ++kc) {
        uint32_t ah[2][4], al[2][4];
        #pragma unroll
        for (int mt = 0; mt < 2; ++mt) {
            int row  = wm*32 + mt*16 + (lane & 15);
            int koff = kc*16 + (lane >> 4)*8;
            uint32_t off = row*PADB + koff*2;
            ldsm_x4(ah[mt], smem_base + SM_A   + off);
            ldsm_x4(al[mt], smem_base + SM_ALO + off);
        }
        #pragma unroll
        for (int g = 0; g < 4; ++g) {
            int gg = wn*4 + g;
            uint4 b4h = __ldg(&Bfh[(gg*8 + kc)*32 + lane]);
            uint4 b4l = __ldg(&Bfl[(gg*8 + kc)*32 + lane]);
            #pragma unroll
            for (int mt = 0; mt < 2; ++mt) {
                mma_bf16(acc[mt][2*g+0], ah[mt], b4h.x, b4h.y);
                mma_bf16(acc[mt][2*g+0], ah[mt], b4l.x, b4l.y);
                mma_bf16(acc[mt][2*g+0], al[mt], b4h.x, b4h.y);
                mma_bf16(acc[mt][2*g+1], ah[mt], b4h.z, b4h.w);
                mma_bf16(acc[mt][2*g+1], ah[mt], b4l.z, b4l.w);
                mma_bf16(acc[mt][2*g+1], al[mt], b4h.z, b4h.w);
            }
        }
    }

    // ---- stage accumulators to smem (overlays A) ----
    __syncthreads();
    float* stage = (float*)(smem + SM_STAGE);
    {
        int g = lane >> 2, t2 = (lane & 3)*2;
        #pragma unroll
        for (int mt = 0; mt < 2; ++mt) {
            #pragma unroll
            for (int nt = 0; nt < 8; ++nt) {
                int r0 = wm*32 + mt*16 + g;
                int c0 = wn*64 + nt*8 + t2;
                *(float2*)(stage + r0*STG_STRIDE + c0)     = make_float2(acc[mt][nt][0], acc[mt][nt][1]);
                *(float2*)(stage + (r0+8)*STG_STRIDE + c0) = make_float2(acc[mt][nt][2], acc[mt][nt][3]);
            }
        }
    }
    __syncthreads();

    // ---- epilogue: row-per-warp, coalesced; bias + e1-CSR + store (+pred) ----
    {
        int kcol = lane*4;
        float4 b4 = *(const float4*)(sBias + kcol);
        float4 wa = make_float4(0,0,0,0), wb = make_float4(0,0,0,0);
        float bo0 = 0.f, bo1 = 0.f;
        if (MODE == 2) {
            wa = *(const float4*)(sEx + 2*kcol);
            wb = *(const float4*)(sEx + 2*kcol + 4);
            bo0 = bout[0]; bo1 = bout[1];
        }
        #pragma unroll 2
        for (int i = 0; i < 16; ++i) {
            int lrow = wid*16 + i;
            long orow = blockRow + lrow;
            bool ok = orow < M;
            long rc = ok ? orow : (M-1);
            int beg = __ldg(rowptr + rc);
            int end = __ldg(rowptr + rc + 1);
            float4 t4 = *(const float4*)(stage + lrow*STG_STRIDE + kcol);
            float4 v = make_float4(t4.x + b4.x, t4.y + b4.y, t4.z + b4.z, t4.w + b4.w);
            for (int e = beg; e < end; ++e) {
                float4 u = *(const float4*)(tuser + (size_t)csrc[e]*H + kcol);
                v.x += u.x; v.y += u.y; v.z += u.z; v.w += u.w;
            }
            if (ok) *(float4*)(C + orow*H + kcol) = v;
            if (MODE == 2) {
                float z0 = v.x*wa.x + v.y*wa.z + v.z*wb.x + v.w*wb.z;
                float z1 = v.x*wa.y + v.y*wa.w + v.z*wb.y + v.w*wb.w;
                #pragma unroll
                for (int o = 16; o > 0; o >>= 1) {
                    z0 += __shfl_xor_sync(0xffffffffu, z0, o);
                    z1 += __shfl_xor_sync(0xffffffffu, z1, o);
                }
                if (lane == 0 && ok) {
                    z0 += bo0; z1 += bo1;
                    float m = fmaxf(z0, z1);
                    float l = m + logf(expf(z0 - m) + expf(z1 - m));
                    *(float2*)(pred + orow*2) = make_float2(z0 - l, z1 - l);
                }
            }
        }
    }
}

// ---------------- launch ----------------
extern "C" void kernel_launch(void* const* d_in, const int* in_sizes, int n_in,
                              void* d_out, int out_size) {
    const float* x_ud   = (const float*)d_in[0];
    const float* W_feat = (const float*)d_in[1];
    const float* b_feat = (const float*)d_in[2];
    const float* emb_ud = (const float*)d_in[3];
    const float* emb_us = (const float*)d_in[4];
    const float* emb_sp = (const float*)d_in[5];
    const float* Wr1 = (const float*)d_in[6];
    const float* br1 = (const float*)d_in[7];
    const float* Wt1 = (const float*)d_in[8];
    const float* Wr2 = (const float*)d_in[9];
    const float* br2 = (const float*)d_in[10];
    const float* Wt2 = (const float*)d_in[11];
    const float* Wout = (const float*)d_in[12];
    const float* bout = (const float*)d_in[13];
    const int* nid_ud = (const int*)d_in[14];
    const int* nid_us = (const int*)d_in[15];
    const int* nid_sp = (const int*)d_in[16];
    const int* e0s = (const int*)d_in[17];
    const int* e0d = (const int*)d_in[18];
    const int* e1s = (const int*)d_in[19];
    const int* e1d = (const int*)d_in[20];
    const int* e2s = (const int*)d_in[21];
    const int* e2d = (const int*)d_in[22];
    const int* e3s = (const int*)d_in[23];
    const int* e3d = (const int*)d_in[24];

    float *p_hud1, *p_user0, *p_user1, *p_sup0, *p_sup1, *p_tuser, *p_agg;
    int *p_rowptr, *p_csrc;
    uint4 *p_bfh, *p_bfl;
    cudaGetSymbolAddress((void**)&p_hud1,  g_hud1);
    cudaGetSymbolAddress((void**)&p_user0, g_user0);
    cudaGetSymbolAddress((void**)&p_user1, g_user1);
    cudaGetSymbolAddress((void**)&p_sup0,  g_sup0);
    cudaGetSymbolAddress((void**)&p_sup1,  g_sup1);
    cudaGetSymbolAddress((void**)&p_tuser, g_tuser);
    cudaGetSymbolAddress((void**)&p_agg,   g_agg);
    cudaGetSymbolAddress((void**)&p_rowptr, g_rowptr);
    cudaGetSymbolAddress((void**)&p_csrc,   g_csrc);
    cudaGetSymbolAddress((void**)&p_bfh,    g_Bfh);
    cudaGetSymbolAddress((void**)&p_bfl,    g_Bfl);

    float* out    = (float*)d_out;
    float* o_pred = out;
    float* o_hud  = out + 1000000;
    float* o_user = out + 65000000;
    float* o_sup  = out + 65512000;

    cudaFuncSetAttribute(k_fused_mma<1>, cudaFuncAttributeMaxDynamicSharedMemorySize, TC_SMEM);
    cudaFuncSetAttribute(k_fused_mma<2>, cudaFuncAttributeMaxDynamicSharedMemorySize, TC_SMEM);

    const int T = 256;
    int gridUs32  = (N_USER*32 + T-1)/T;
    int gridSp32  = (N_SUP*32 + T-1)/T;
    int gridES    = (E_SMALL*32 + T-1)/T;
    int gridClean = (NA/4 + T-1)/T;

    // ---- init (3 launches) ----
    k_combo<<<CB_TOT, T>>>(Wt1, Wt2, emb_us, nid_us, emb_sp, nid_sp, e1d, e0d);
    k_scan1<<<SCAN_BLK, SCAN_T>>>();
    k_fill_tuser<<<FT_F + FT_G, T>>>(e1s, e1d, e0s, e0d, p_user0, Wr1 + 1*HH);

    // ---- slot 4 (ncu-profiled): e0 L1 aggregation (algebraic split) ----
    k_agg_feat<<<N_USER, 128>>>(x_ud, nid_ud, emb_ud, W_feat, b_feat,
                                p_rowptr, p_csrc, p_agg + L1_UB);

    // ---- layer 1 UD: fused feat+GEMM+e1 CSR ----
    k_fused_mma<1><<<N_TILES, 256, TC_SMEM>>>(
        br1 + 1*H, p_tuser, p_rowptr, p_csrc, p_hud1,
        nullptr, x_ud, nid_ud, emb_ud, W_feat, b_feat,
        nullptr, nullptr, nullptr, p_bfh, p_bfl, N_UD);

    // ---- layer 1 small aggregations ----
    k_edge_add<<<gridES, T>>>(p_sup0,  e3s, e3d, p_agg + L1_US, E_SMALL);
    k_edge_add<<<gridES, T>>>(p_user0, e2s, e2d, p_agg + L1_S,  E_SMALL);

    // ---- layer 1 user/sup outputs (post-relu stored) ----
    k_gemm_small<<<gridUs32, T>>>(p_agg + L1_UB, Wr1 + 0*HH, br1 + 0*H, p_user1, N_USER, 0, 0);
    k_gemm_small<<<gridUs32, T>>>(p_agg + L1_US, Wr1 + 3*HH, br1 + 3*H, p_user1, N_USER, 1, 0);
    k_gemm_small<<<gridUs32, T>>>(p_user0,       Wt1 + 0*HH, nullptr,   p_user1, N_USER, 1, 0);
    k_gemm_small<<<gridUs32, T>>>(p_user0,       Wt1 + 3*HH, nullptr,   p_user1, N_USER, 1, 1);
    k_gemm_small<<<gridSp32, T>>>(p_agg + L1_S,  Wr1 + 2*HH, br1 + 2*H, p_sup1,  N_SUP,  0, 0);
    k_gemm_small<<<gridSp32, T>>>(p_sup0,        Wt1 + 2*HH, nullptr,   p_sup1,  N_SUP,  1, 1);

    // ---- layer 2: tuser2, fused relu+GEMM+e1 CSR+pred ----
    k_gemm_small<<<gridUs32, T>>>(p_user1, Wr2 + 1*HH, nullptr, p_tuser, N_USER, 0, 0);
    k_fused_mma<2><<<N_TILES, 256, TC_SMEM>>>(
        br2 + 1*H, p_tuser, p_rowptr, p_csrc, o_hud,
        p_hud1, nullptr, nullptr, nullptr, nullptr, nullptr,
        Wout, bout, o_pred, p_bfh + 2048, p_bfl + 2048, N_UD);

    // ---- layer 2 aggregations + user/sup outputs ----
    k_agg_user<<<N_USER, 128>>>(p_hud1, p_rowptr, p_csrc, p_agg + L2_UB);
    k_edge_add<<<gridES, T>>>(p_sup1,  e3s, e3d, p_agg + L2_US, E_SMALL);
    k_edge_add<<<gridES, T>>>(p_user1, e2s, e2d, p_agg + L2_S,  E_SMALL);
    k_gemm_small<<<gridUs32, T>>>(p_agg + L2_UB, Wr2 + 0*HH, br2 + 0*H, o_user, N_USER, 0, 0);
    k_gemm_small<<<gridUs32, T>>>(p_agg + L2_US, Wr2 + 3*HH, br2 + 3*H, o_user, N_USER, 1, 0);
    k_gemm_small<<<gridUs32, T>>>(p_user1,       Wt2 + 0*HH, nullptr,   o_user, N_USER, 1, 0);
    k_gemm_small<<<gridUs32, T>>>(p_user1,       Wt2 + 3*HH, nullptr,   o_user, N_USER, 1, 0);
    k_gemm_small<<<gridSp32, T>>>(p_agg + L2_S,  Wr2 + 2*HH, br2 + 2*H, o_sup,  N_SUP,  0, 0);
    k_gemm_small<<<gridSp32, T>>>(p_sup1,        Wt2 + 2*HH, nullptr,   o_sup,  N_SUP,  1, 0);

    // ---- cleanup ----
    k_cleanup<<<gridClean, T>>>();

    (void)in_sizes; (void)n_in; (void)out_size;
}